// round 5
// baseline (speedup 1.0000x reference)
#include <cuda_runtime.h>
#include <cstdint>

// Problem constants
#define NROWS   131072
#define DDIM    256
#define NW      256     // codewords
#define NB      8       // books
#define LW      32      // dims per book
#define TAUQ    5.0f

#define Z_ELEMS   (NROWS * DDIM)          // 33554432
#define IDX_ELEMS (NROWS * NB)            // 1048576
#define C_ELEMS   (NW * DDIM)             // 65536

#define KEY_MARGIN 1e-3f                  // packed-vs-exact key bound is ~1e-6
#define RPT 2                             // rows per thread

// ---------- packed f32x2 helpers ----------
__device__ __forceinline__ unsigned long long pack2(float lo, float hi) {
    unsigned long long r;
    asm("mov.b64 %0, {%1, %2};" : "=l"(r) : "r"(__float_as_uint(lo)), "r"(__float_as_uint(hi)));
    return r;
}
__device__ __forceinline__ void unpack2(unsigned long long v, float& lo, float& hi) {
    unsigned a, b;
    asm("mov.b64 {%0, %1}, %2;" : "=r"(a), "=r"(b) : "l"(v));
    lo = __uint_as_float(a); hi = __uint_as_float(b);
}
__device__ __forceinline__ unsigned long long fma2(unsigned long long a, unsigned long long b, unsigned long long c) {
    unsigned long long d;
    asm("fma.rn.f32x2 %0, %1, %2, %3;" : "=l"(d) : "l"(a), "l"(b), "l"(c));
    return d;
}
// 128-bit broadcast shared load -> two packed u64
__device__ __forceinline__ void lds128(unsigned addr, unsigned long long& p0, unsigned long long& p1) {
    unsigned a, b, c, d;
    asm volatile("ld.shared.v4.b32 {%0,%1,%2,%3}, [%4];"
                 : "=r"(a), "=r"(b), "=r"(c), "=r"(d) : "r"(addr));
    asm("mov.b64 %0, {%1, %2};" : "=l"(p0) : "r"(a), "r"(b));
    asm("mov.b64 %0, {%1, %2};" : "=l"(p1) : "r"(c), "r"(d));
}

// Butterfly-tree sum of 32 separately-rounded squares (matches reference).
__device__ __forceinline__ float tree_sumsq32(const float* v) {
    float s[32];
    #pragma unroll
    for (int i = 0; i < 32; ++i) s[i] = __fmul_rn(v[i], v[i]);
    #pragma unroll
    for (int stride = 16; stride >= 1; stride >>= 1) {
        #pragma unroll
        for (int i = 0; i < stride; ++i) s[i] = __fadd_rn(s[i], s[i + stride]);
    }
    return s[0];
}

// One CTA = 256 threads x RPT rows x 1 book.
__global__ __launch_bounds__(256)
void softpq_kernel(const float* __restrict__ x, const float* __restrict__ C,
                   float* __restrict__ out)
{
    __shared__ float sC[NW * LW];   // codebook slice for this book [256][32]
    __shared__ float sc2[NW];       // c2 via butterfly-tree chain

    const int tid  = threadIdx.x;
    const int book = blockIdx.y;
    const int n0   = blockIdx.x * (256 * RPT) + tid;   // rows n0, n0+256

    // Load Cr slice (thread tid -> codeword tid), c2 via tree reduction.
    {
        const float4* src = reinterpret_cast<const float4*>(C);
        float4* dst = reinterpret_cast<float4*>(sC);
        float cv[32];
        #pragma unroll
        for (int j = 0; j < 8; ++j) {
            float4 v = src[tid * (DDIM/4) + book * (LW/4) + j];
            cv[4*j+0] = v.x; cv[4*j+1] = v.y; cv[4*j+2] = v.z; cv[4*j+3] = v.w;
            dst[tid * (LW/4) + j] = v;
        }
        sc2[tid] = tree_sumsq32(cv);
    }
    __syncthreads();

    // Load RPT row sub-vectors; x2 via the same tree chain.
    unsigned long long xr2[RPT][16];
    float X2[RPT], kshift[RPT];
    {
        const float4* xs = reinterpret_cast<const float4*>(x);
        #pragma unroll
        for (int r = 0; r < RPT; ++r) {
            float xv[32];
            size_t n = (size_t)n0 + r * 256;
            #pragma unroll
            for (int j = 0; j < 8; ++j) {
                float4 v = xs[n * (DDIM/4) + book * (LW/4) + j];
                xv[4*j+0] = v.x; xv[4*j+1] = v.y; xv[4*j+2] = v.z; xv[4*j+3] = v.w;
                xr2[r][2*j]   = pack2(v.x, v.y);
                xr2[r][2*j+1] = pack2(v.z, v.w);
            }
            X2[r] = tree_sumsq32(xv);
            kshift[r] = TAUQ * X2[r];
        }
    }

    const unsigned long long zero64 = pack2(0.f, 0.f);
    unsigned long long z2[RPT][16];
    #pragma unroll
    for (int r = 0; r < RPT; ++r)
        #pragma unroll
        for (int k = 0; k < 16; ++k) z2[r][k] = zero64;

    float ssum[RPT], bestKey[RPT];
    int best[RPT];
    #pragma unroll
    for (int r = 0; r < RPT; ++r) { ssum[r] = 0.f; bestKey[r] = -3.4e38f; best[r] = 0; }

    const unsigned sbase = (unsigned)__cvta_generic_to_shared(sC);

    #pragma unroll 1
    for (int w = 0; w < NW; ++w) {
        unsigned a = sbase + (unsigned)(w * (LW * 4));
        unsigned long long cr[16];
        #pragma unroll
        for (int k = 0; k < 8; ++k) lds128(a + k * 16, cr[2*k], cr[2*k+1]);

        const float c2w = sc2[w];

        #pragma unroll
        for (int r = 0; r < RPT; ++r) {
            // Fast packed dot for the softmax/Z path
            unsigned long long acc = zero64;
            #pragma unroll
            for (int k = 0; k < 16; ++k) acc = fma2(xr2[r][k], cr[k], acc);
            float dlo, dhi; unpack2(acc, dlo, dhi);
            float dotA = dlo + dhi;

            float tA = X2[r] + c2w;
            float keyA = -TAUQ * fmaf(-2.0f, dotA, tA);

            // Candidate? Recompute key with the reference's exact rounding chain.
            if (keyA > bestKey[r] - KEY_MARGIN) {
                float de = 0.f;
                #pragma unroll
                for (int k = 0; k < 16; ++k) {
                    float x0, x1, c0, c1;
                    unpack2(xr2[r][k], x0, x1);
                    unpack2(cr[k],  c0, c1);
                    de = __fmaf_rn(x0, c0, de);
                    de = __fmaf_rn(x1, c1, de);
                }
                float t    = __fadd_rn(X2[r], c2w);
                float dist = __fmaf_rn(-2.0f, de, t);
                float key  = __fmul_rn(-TAUQ, dist);
                if (key > bestKey[r]) { bestKey[r] = key; best[r] = w; }
            }

            // Softmax/Z accumulation
            float p = __expf(keyA + kshift[r]);
            ssum[r] += p;
            unsigned long long p2 = pack2(p, p);
            #pragma unroll
            for (int k = 0; k < 16; ++k) z2[r][k] = fma2(p2, cr[k], z2[r][k]);
        }
    }

    // Write Z (float4 stores) and idx
    {
        float4* zo = reinterpret_cast<float4*>(out);
        #pragma unroll
        for (int r = 0; r < RPT; ++r) {
            const float invs = 1.0f / ssum[r];
            size_t n = (size_t)n0 + r * 256;
            #pragma unroll
            for (int j = 0; j < 8; ++j) {
                float a0, a1, a2, a3;
                unpack2(z2[r][2*j],   a0, a1);
                unpack2(z2[r][2*j+1], a2, a3);
                float4 v = make_float4(a0 * invs, a1 * invs, a2 * invs, a3 * invs);
                zo[n * (DDIM/4) + book * (LW/4) + j] = v;
            }
            out[(size_t)Z_ELEMS + n * NB + book] = (float)best[r];
        }
    }
}

// Copy C to tail of output
__global__ void copy_c_kernel(const float* __restrict__ C, float* __restrict__ out)
{
    int i = blockIdx.x * blockDim.x + threadIdx.x;
    if (i < C_ELEMS) out[(size_t)Z_ELEMS + IDX_ELEMS + i] = C[i];
}

extern "C" void kernel_launch(void* const* d_in, const int* in_sizes, int n_in,
                              void* d_out, int out_size)
{
    const float* x = (const float*)d_in[0];
    const float* C = (const float*)d_in[1];
    float* out = (float*)d_out;

    dim3 grid(NROWS / (256 * RPT), NB);
    softpq_kernel<<<grid, 256>>>(x, C, out);
    copy_c_kernel<<<(C_ELEMS + 255) / 256, 256>>>(C, out);
}

// round 6
// speedup vs baseline: 1.1170x; 1.1170x over previous
#include <cuda_runtime.h>
#include <cstdint>

// Problem constants
#define NROWS   131072
#define DDIM    256
#define NW      256     // codewords
#define NB      8       // books
#define LW      32      // dims per book
#define TAUQ    5.0f

#define Z_ELEMS   (NROWS * DDIM)          // 33554432
#define IDX_ELEMS (NROWS * NB)            // 1048576
#define C_ELEMS   (NW * DDIM)             // 65536

#define QMARGIN 1.5e-4f   // covers ref-chain quantization (~5e-5) + dot err (~1e-5)

// ---------- packed f32x2 helpers ----------
__device__ __forceinline__ unsigned long long pack2(float lo, float hi) {
    unsigned long long r;
    asm("mov.b64 %0, {%1, %2};" : "=l"(r) : "r"(__float_as_uint(lo)), "r"(__float_as_uint(hi)));
    return r;
}
__device__ __forceinline__ void unpack2(unsigned long long v, float& lo, float& hi) {
    unsigned a, b;
    asm("mov.b64 {%0, %1}, %2;" : "=r"(a), "=r"(b) : "l"(v));
    lo = __uint_as_float(a); hi = __uint_as_float(b);
}
__device__ __forceinline__ unsigned long long fma2(unsigned long long a, unsigned long long b, unsigned long long c) {
    unsigned long long d;
    asm("fma.rn.f32x2 %0, %1, %2, %3;" : "=l"(d) : "l"(a), "l"(b), "l"(c));
    return d;
}
// 128-bit broadcast shared load -> two packed u64
__device__ __forceinline__ void lds128(unsigned addr, unsigned long long& p0, unsigned long long& p1) {
    unsigned a, b, c, d;
    asm volatile("ld.shared.v4.b32 {%0,%1,%2,%3}, [%4];"
                 : "=r"(a), "=r"(b), "=r"(c), "=r"(d) : "r"(addr));
    asm("mov.b64 %0, {%1, %2};" : "=l"(p0) : "r"(a), "r"(b));
    asm("mov.b64 %0, {%1, %2};" : "=l"(p1) : "r"(c), "r"(d));
}

// Butterfly-tree sum of 32 separately-rounded squares (matches reference).
__device__ __forceinline__ float tree_sumsq32(const float* v) {
    float s[32];
    #pragma unroll
    for (int i = 0; i < 32; ++i) s[i] = __fmul_rn(v[i], v[i]);
    #pragma unroll
    for (int stride = 16; stride >= 1; stride >>= 1) {
        #pragma unroll
        for (int i = 0; i < stride; ++i) s[i] = __fadd_rn(s[i], s[i + stride]);
    }
    return s[0];
}

// One CTA = 256 rows x 1 book. Each thread owns one (row, book).
__global__ __launch_bounds__(256, 2)
void softpq_kernel(const float* __restrict__ x, const float* __restrict__ C,
                   float* __restrict__ out)
{
    __shared__ float sC[NW * LW];   // codebook slice for this book [256][32]
    __shared__ float sc2[NW];       // c2 via butterfly-tree chain (exact-path input)
    __shared__ float s5c2[NW];      // 5*c2 for the cheap monotone key

    const int tid  = threadIdx.x;
    const int book = blockIdx.y;
    const int n    = blockIdx.x * 256 + tid;

    // Load Cr slice (thread tid -> codeword tid), c2 via tree reduction.
    {
        const float4* src = reinterpret_cast<const float4*>(C);
        float4* dst = reinterpret_cast<float4*>(sC);
        float cv[32];
        #pragma unroll
        for (int j = 0; j < 8; ++j) {
            float4 v = src[tid * (DDIM/4) + book * (LW/4) + j];
            cv[4*j+0] = v.x; cv[4*j+1] = v.y; cv[4*j+2] = v.z; cv[4*j+3] = v.w;
            dst[tid * (LW/4) + j] = v;
        }
        float c2 = tree_sumsq32(cv);
        sc2[tid]  = c2;
        s5c2[tid] = TAUQ * c2;
    }
    __syncthreads();

    // Load this thread's x sub-vector; x2 via the same tree chain.
    unsigned long long xr2[16];
    float xv[32];
    {
        const float4* xs = reinterpret_cast<const float4*>(x);
        #pragma unroll
        for (int j = 0; j < 8; ++j) {
            float4 v = xs[(size_t)n * (DDIM/4) + book * (LW/4) + j];
            xv[4*j+0] = v.x; xv[4*j+1] = v.y; xv[4*j+2] = v.z; xv[4*j+3] = v.w;
            xr2[2*j]   = pack2(v.x, v.y);
            xr2[2*j+1] = pack2(v.z, v.w);
        }
    }
    const float X2 = tree_sumsq32(xv);

    const unsigned long long zero64 = pack2(0.f, 0.f);
    unsigned long long z2[16];
    #pragma unroll
    for (int k = 0; k < 16; ++k) z2[k] = zero64;

    float ssum = 0.f;
    // Top-4 candidates by cheap key q = 10*dot - 5*c2 (ordering == key ordering)
    float q0 = -3.4e38f, q1 = -3.4e38f, q2 = -3.4e38f, q3 = -3.4e38f;
    int   i0 = -1, i1 = -1, i2 = -1, i3 = -1;

    const unsigned sbase = (unsigned)__cvta_generic_to_shared(sC);

    #pragma unroll 1
    for (int w = 0; w < NW; ++w) {
        unsigned a = sbase + (unsigned)(w * (LW * 4));
        unsigned long long cr[16];
        #pragma unroll
        for (int k = 0; k < 8; ++k) lds128(a + k * 16, cr[2*k], cr[2*k+1]);

        // Packed dot
        unsigned long long acc = zero64;
        #pragma unroll
        for (int k = 0; k < 16; ++k) acc = fma2(xr2[k], cr[k], acc);
        float dlo, dhi; unpack2(acc, dlo, dhi);
        float dot = dlo + dhi;

        float q = fmaf(10.0f, dot, -s5c2[w]);   // monotone argmax key (approx)

        // Top-4 insertion (predicated sel network; rare shifts after warmup)
        if (q > q3) {
            if (q > q0)      { q3=q2; i3=i2; q2=q1; i2=i1; q1=q0; i1=i0; q0=q; i0=w; }
            else if (q > q1) { q3=q2; i3=i2; q2=q1; i2=i1; q1=q;  i1=w; }
            else if (q > q2) { q3=q2; i3=i2; q2=q;  i2=w; }
            else             { q3=q;  i3=w; }
        }

        // Softmax/Z accumulation: softmax shift-invariant -> use exp(q)
        float p = __expf(q);
        ssum += p;
        unsigned long long p2 = pack2(p, p);
        #pragma unroll
        for (int k = 0; k < 16; ++k) z2[k] = fma2(p2, cr[k], z2[k]);
    }

    // Post-loop exact recheck of candidates within margin, using the
    // reference's exact rounding chain (ascending-k FFMA dot; tree norms).
    int best = 0;
    {
        float bestKey = -3.4e38f;
        int   bestW   = NW;          // for first-index tie-break
        const float qthr = q0 - QMARGIN;
        float qs[4] = {q0, q1, q2, q3};
        int   is[4] = {i0, i1, i2, i3};
        #pragma unroll
        for (int c = 0; c < 4; ++c) {
            int w = is[c];
            if (w < 0 || qs[c] < qthr) continue;
            const float* cw = sC + w * LW;
            float de = 0.f;
            #pragma unroll
            for (int k = 0; k < 32; ++k) de = __fmaf_rn(xv[k], cw[k], de);
            float t    = __fadd_rn(X2, sc2[w]);
            float dist = __fmaf_rn(-2.0f, de, t);
            float key  = __fmul_rn(-TAUQ, dist);
            if (key > bestKey || (key == bestKey && w < bestW)) { bestKey = key; bestW = w; }
        }
        best = bestW;
    }

    const float invs = 1.0f / ssum;

    // Write Z (float4 stores)
    {
        float4* zo = reinterpret_cast<float4*>(out);
        #pragma unroll
        for (int j = 0; j < 8; ++j) {
            float a0, a1, a2, a3;
            unpack2(z2[2*j],   a0, a1);
            unpack2(z2[2*j+1], a2, a3);
            float4 v = make_float4(a0 * invs, a1 * invs, a2 * invs, a3 * invs);
            zo[(size_t)n * (DDIM/4) + book * (LW/4) + j] = v;
        }
    }

    // Write idx (as float, numeric cast)
    out[(size_t)Z_ELEMS + (size_t)n * NB + book] = (float)best;
}

// Copy C to tail of output
__global__ void copy_c_kernel(const float* __restrict__ C, float* __restrict__ out)
{
    int i = blockIdx.x * blockDim.x + threadIdx.x;
    if (i < C_ELEMS) out[(size_t)Z_ELEMS + IDX_ELEMS + i] = C[i];
}

extern "C" void kernel_launch(void* const* d_in, const int* in_sizes, int n_in,
                              void* d_out, int out_size)
{
    const float* x = (const float*)d_in[0];
    const float* C = (const float*)d_in[1];
    float* out = (float*)d_out;

    dim3 grid(NROWS / 256, NB);
    softpq_kernel<<<grid, 256>>>(x, C, out);
    copy_c_kernel<<<(C_ELEMS + 255) / 256, 256>>>(C, out);
}